// round 2
// baseline (speedup 1.0000x reference)
#include <cuda_runtime.h>

#define SEQ    2048
#define DMODEL 2048
#define NHEADS 32
#define DHEAD  64

// Scratch (allocation-free rule: __device__ globals)
__device__ float g_Q[SEQ * DMODEL];
__device__ float g_K[SEQ * DMODEL];
__device__ float g_V[SEQ * DMODEL];
__device__ float g_Qh[SEQ * DMODEL];   // [h][l][d] layout, Q pre-scaled
__device__ float g_Kh[SEQ * DMODEL];
__device__ float g_Vh[SEQ * DMODEL];
__device__ float g_ctx[SEQ * DMODEL];  // attention output in [l][d*32+h] layout

// ---------------------------------------------------------------------------
// NT SGEMM: C[M,N] = A[M,K] @ W[N,K]^T + bias[N], M=N=K=2048, row-major.
// 128x128 block tile, BK=8, 8x8 per-thread microtile, 256 threads.
// ---------------------------------------------------------------------------
__device__ __forceinline__ void gemm_nt_body(
    const float* __restrict__ A, const float* __restrict__ W,
    const float* __restrict__ bias, float* __restrict__ C)
{
    __shared__ float As[8][128];
    __shared__ float Bs[8][128];

    const int t    = threadIdx.x;
    const int tx   = t & 15;
    const int ty   = t >> 4;
    const int row0 = blockIdx.y * 128;
    const int col0 = blockIdx.x * 128;
    const int lrow = t >> 1;         // 0..127
    const int lk   = (t & 1) * 4;    // 0 or 4

    float acc[8][8];
#pragma unroll
    for (int i = 0; i < 8; i++)
#pragma unroll
        for (int j = 0; j < 8; j++) acc[i][j] = 0.f;

    for (int k0 = 0; k0 < DMODEL; k0 += 8) {
        float4 av = *(const float4*)&A[(row0 + lrow) * DMODEL + k0 + lk];
        float4 bv = *(const float4*)&W[(col0 + lrow) * DMODEL + k0 + lk];
        As[lk + 0][lrow] = av.x; As[lk + 1][lrow] = av.y;
        As[lk + 2][lrow] = av.z; As[lk + 3][lrow] = av.w;
        Bs[lk + 0][lrow] = bv.x; Bs[lk + 1][lrow] = bv.y;
        Bs[lk + 2][lrow] = bv.z; Bs[lk + 3][lrow] = bv.w;
        __syncthreads();
#pragma unroll
        for (int kk = 0; kk < 8; kk++) {
            float ar[8], br[8];
            *(float4*)&ar[0] = *(const float4*)&As[kk][ty * 8];
            *(float4*)&ar[4] = *(const float4*)&As[kk][ty * 8 + 4];
            *(float4*)&br[0] = *(const float4*)&Bs[kk][tx * 8];
            *(float4*)&br[4] = *(const float4*)&Bs[kk][tx * 8 + 4];
#pragma unroll
            for (int i = 0; i < 8; i++)
#pragma unroll
                for (int j = 0; j < 8; j++)
                    acc[i][j] += ar[i] * br[j];
        }
        __syncthreads();
    }

    float bb[8];
#pragma unroll
    for (int j = 0; j < 8; j++) bb[j] = bias[col0 + tx * 8 + j];
#pragma unroll
    for (int i = 0; i < 8; i++) {
        float4 v0, v1;
        v0.x = acc[i][0] + bb[0]; v0.y = acc[i][1] + bb[1];
        v0.z = acc[i][2] + bb[2]; v0.w = acc[i][3] + bb[3];
        v1.x = acc[i][4] + bb[4]; v1.y = acc[i][5] + bb[5];
        v1.z = acc[i][6] + bb[6]; v1.w = acc[i][7] + bb[7];
        float* cp = &C[(row0 + ty * 8 + i) * DMODEL + col0 + tx * 8];
        *(float4*)&cp[0] = v0;
        *(float4*)&cp[4] = v1;
    }
}

__global__ void __launch_bounds__(256) qkv_gemm_kernel(
    const float* __restrict__ X,
    const float* __restrict__ Wq, const float* __restrict__ bq,
    const float* __restrict__ Wk, const float* __restrict__ bk,
    const float* __restrict__ Wv, const float* __restrict__ bv)
{
    const float* W; const float* b; float* C;
    if (blockIdx.z == 0)      { W = Wq; b = bq; C = g_Q; }
    else if (blockIdx.z == 1) { W = Wk; b = bk; C = g_K; }
    else                      { W = Wv; b = bv; C = g_V; }
    gemm_nt_body(X, W, b, C);
}

__global__ void __launch_bounds__(256) out_gemm_kernel(
    const float* __restrict__ Wo, const float* __restrict__ bo,
    float* __restrict__ out)
{
    gemm_nt_body(g_ctx, Wo, bo, out);
}

// ---------------------------------------------------------------------------
// Head transpose: [l][d*32+h] -> [h][l][d] (d contiguous), coalesced both ways
// via padded smem ([l][h][d] with h-stride 65 to dodge bank conflicts).
// blockIdx.x: l-tile of 4 rows (512 tiles); blockIdx.y: tensor 0=Q,1=K,2=V.
// Q is pre-scaled by 1/sqrt(D_MODEL).
// ---------------------------------------------------------------------------
__global__ void __launch_bounds__(256) head_transpose_kernel()
{
    const float* src; float* dst; float scale;
    if (blockIdx.y == 0)      { src = g_Q; dst = g_Qh; scale = rsqrtf((float)DMODEL); }
    else if (blockIdx.y == 1) { src = g_K; dst = g_Kh; scale = 1.f; }
    else                      { src = g_V; dst = g_Vh; scale = 1.f; }

    __shared__ float s[4 * 2080];   // [l][h][d]: l*2080 + h*65 + d
    const int t  = threadIdx.x;
    const int l0 = blockIdx.x * 4;

#pragma unroll
    for (int i = 0; i < 8; i++) {
        int f4 = t + 256 * i;             // 0..2047 float4s (4 rows x 512)
        int l  = f4 >> 9;                 // 512 float4 per row
        int n  = (f4 & 511) * 4;
        float4 v = *(const float4*)&src[(l0 + l) * DMODEL + n];
        s[l * 2080 + ((n + 0) & 31) * 65 + ((n + 0) >> 5)] = v.x * scale;
        s[l * 2080 + ((n + 1) & 31) * 65 + ((n + 1) >> 5)] = v.y * scale;
        s[l * 2080 + ((n + 2) & 31) * 65 + ((n + 2) >> 5)] = v.z * scale;
        s[l * 2080 + ((n + 3) & 31) * 65 + ((n + 3) >> 5)] = v.w * scale;
    }
    __syncthreads();

#pragma unroll
    for (int i = 0; i < 8; i++) {
        int f4 = t + 256 * i;             // flat over h(32) x l(4) x d4(16)
        int d  = (f4 & 15) * 4;
        int l  = (f4 >> 4) & 3;
        int hh = f4 >> 6;
        int base = l * 2080 + hh * 65 + d;
        float4 v;
        v.x = s[base + 0]; v.y = s[base + 1];
        v.z = s[base + 2]; v.w = s[base + 3];
        *(float4*)&dst[hh * (SEQ * DHEAD) + (l0 + l) * DHEAD + d] = v;
    }
}

// ---------------------------------------------------------------------------
// Flash attention, fp32. One block = (head, 64-query tile); streams 32-key
// tiles. 256 threads. Q pre-scaled, so S = Qs . Ks directly.
// ---------------------------------------------------------------------------
__global__ void __launch_bounds__(256) attn_kernel()
{
    const int h  = blockIdx.y;
    const int q0 = blockIdx.x * 64;
    const float* __restrict__ Qh = g_Qh + h * (SEQ * DHEAD);
    const float* __restrict__ Kh = g_Kh + h * (SEQ * DHEAD);
    const float* __restrict__ Vh = g_Vh + h * (SEQ * DHEAD);

    __shared__ float Qs[64][68];
    __shared__ float Ks[32][68];
    __shared__ float Vs[32][68];
    __shared__ float Ss[64][36];
    __shared__ float alpha_s[64];
    __shared__ float ls[64];

    const int t  = threadIdx.x;
    const int tx = t & 15;
    const int ty = t >> 4;

    // Load Q tile 64x64 (coalesced)
#pragma unroll
    for (int i = 0; i < 4; i++) {
        int f4 = t + 256 * i;            // 0..1023
        int r  = f4 >> 4;
        int d  = (f4 & 15) * 4;
        *(float4*)&Qs[r][d] = *(const float4*)&Qh[(q0 + r) * DHEAD + d];
    }

    float m_r = -1e30f, l_r = 0.f;       // softmax-role row = t>>2
    float Oacc[4][4];
#pragma unroll
    for (int i = 0; i < 4; i++)
#pragma unroll
        for (int j = 0; j < 4; j++) Oacc[i][j] = 0.f;

    for (int kt = 0; kt < SEQ / 32; kt++) {
        const int k0 = kt * 32;
        // Load K,V tiles 32x64 (coalesced)
#pragma unroll
        for (int i = 0; i < 2; i++) {
            int f4 = t + 256 * i;        // 0..511
            int r  = f4 >> 4;
            int d  = (f4 & 15) * 4;
            *(float4*)&Ks[r][d] = *(const float4*)&Kh[(k0 + r) * DHEAD + d];
            *(float4*)&Vs[r][d] = *(const float4*)&Vh[(k0 + r) * DHEAD + d];
        }
        __syncthreads();

        // S = Q K^T : rows ty*4..+3, cols tx*2..+1
        float sacc[4][2];
#pragma unroll
        for (int i = 0; i < 4; i++) { sacc[i][0] = 0.f; sacc[i][1] = 0.f; }
#pragma unroll
        for (int k = 0; k < 64; k += 4) {
            float4 q[4], kv[2];
#pragma unroll
            for (int i = 0; i < 4; i++) q[i]  = *(const float4*)&Qs[ty * 4 + i][k];
#pragma unroll
            for (int j = 0; j < 2; j++) kv[j] = *(const float4*)&Ks[tx * 2 + j][k];
#pragma unroll
            for (int i = 0; i < 4; i++)
#pragma unroll
                for (int j = 0; j < 2; j++)
                    sacc[i][j] += q[i].x * kv[j].x + q[i].y * kv[j].y
                                + q[i].z * kv[j].z + q[i].w * kv[j].w;
        }
#pragma unroll
        for (int i = 0; i < 4; i++) {
            Ss[ty * 4 + i][tx * 2 + 0] = sacc[i][0];
            Ss[ty * 4 + i][tx * 2 + 1] = sacc[i][1];
        }
        __syncthreads();

        // Online softmax: row r = t>>2, 8 cols per thread
        {
            const int r  = t >> 2;
            const int c0 = (t & 3) * 8;
            float sv[8];
            float lm = -1e30f;
#pragma unroll
            for (int j = 0; j < 8; j++) { sv[j] = Ss[r][c0 + j]; lm = fmaxf(lm, sv[j]); }
            lm = fmaxf(lm, __shfl_xor_sync(0xffffffffu, lm, 1));
            lm = fmaxf(lm, __shfl_xor_sync(0xffffffffu, lm, 2));
            float mnew  = fmaxf(m_r, lm);
            float alpha = __expf(m_r - mnew);
            float sum = 0.f;
#pragma unroll
            for (int j = 0; j < 8; j++) {
                float p = __expf(sv[j] - mnew);
                Ss[r][c0 + j] = p;
                sum += p;
            }
            sum += __shfl_xor_sync(0xffffffffu, sum, 1);
            sum += __shfl_xor_sync(0xffffffffu, sum, 2);
            l_r = l_r * alpha + sum;
            m_r = mnew;
            if ((t & 3) == 0) { alpha_s[r] = alpha; ls[r] = l_r; }
        }
        __syncthreads();

        // O rescale + PV: rows ty*4..+3, dims tx*4..+3
#pragma unroll
        for (int i = 0; i < 4; i++) {
            float a = alpha_s[ty * 4 + i];
#pragma unroll
            for (int j = 0; j < 4; j++) Oacc[i][j] *= a;
        }
#pragma unroll
        for (int c = 0; c < 32; c++) {
            float4 vv = *(const float4*)&Vs[c][tx * 4];
#pragma unroll
            for (int i = 0; i < 4; i++) {
                float p = Ss[ty * 4 + i][c];
                Oacc[i][0] += p * vv.x;
                Oacc[i][1] += p * vv.y;
                Oacc[i][2] += p * vv.z;
                Oacc[i][3] += p * vv.w;
            }
        }
        __syncthreads();   // protect Ks/Vs/Ss before next iteration's loads
    }

    // Write ctx[(q0+r)][d*32+h], d = tx*4+j
#pragma unroll
    for (int i = 0; i < 4; i++) {
        const int r = ty * 4 + i;
        const float inv = 1.f / ls[r];
#pragma unroll
        for (int j = 0; j < 4; j++) {
            g_ctx[(q0 + r) * DMODEL + (tx * 4 + j) * NHEADS + h] = Oacc[i][j] * inv;
        }
    }
}

// ---------------------------------------------------------------------------
extern "C" void kernel_launch(void* const* d_in, const int* in_sizes, int n_in,
                              void* d_out, int out_size)
{
    (void)in_sizes; (void)n_in; (void)out_size;
    const float* X  = (const float*)d_in[0];
    const float* Wq = (const float*)d_in[1];
    const float* bq = (const float*)d_in[2];
    const float* Wk = (const float*)d_in[3];
    const float* bk = (const float*)d_in[4];
    const float* Wv = (const float*)d_in[5];
    const float* bv = (const float*)d_in[6];
    const float* Wo = (const float*)d_in[7];
    const float* bo = (const float*)d_in[8];
    float* out = (float*)d_out;

    qkv_gemm_kernel<<<dim3(16, 16, 3), 256>>>(X, Wq, bq, Wk, bk, Wv, bv);
    head_transpose_kernel<<<dim3(SEQ / 4, 3), 256>>>();
    attn_kernel<<<dim3(SEQ / 64, NHEADS), 256>>>();
    out_gemm_kernel<<<dim3(16, 16), 256>>>(Wo, bo, out);
}